// round 1
// baseline (speedup 1.0000x reference)
#include <cuda_runtime.h>
#include <math.h>

// Problem constants
#define C_DIM   256
#define N_TOK   4096
#define GROUPS  8
#define CPG     (C_DIM / GROUPS)        // 32
#define HEADS   8
#define HDIM    32
#define EPSV    1e-5f
#define GSIZE   (CPG * N_TOK)           // 131072 elems per group

// ---------------- scratch (static device globals; no allocation) -------------
__device__ float g_part[64][2];                 // per-block partial (sum, sumsq)
__device__ float g_h[C_DIM * N_TOK];            // groupnorm output  [C][N]
__device__ float g_qkv[3 * C_DIM * N_TOK];      // qkv               [3C][N]
__device__ float g_attn[C_DIM * N_TOK];         // attention output  [C][N]

// ---------------- GroupNorm: partial stats (deterministic, no atomics) -------
// grid: 64 blocks (8 groups x 8 slices), 256 threads
__global__ void gn_stats_kernel(const float* __restrict__ x, float* __restrict__ part) {
    int g  = blockIdx.x >> 3;
    int sl = blockIdx.x & 7;
    const float* xg = x + g * GSIZE + sl * (GSIZE / 8);
    float s = 0.f, ss = 0.f;
    for (int i = threadIdx.x; i < GSIZE / 8; i += 256) {
        float v = xg[i];
        s += v; ss += v * v;
    }
    // warp reduce
    for (int o = 16; o > 0; o >>= 1) {
        s  += __shfl_down_sync(0xffffffff, s,  o);
        ss += __shfl_down_sync(0xffffffff, ss, o);
    }
    __shared__ float rs[8], rss[8];
    int wid = threadIdx.x >> 5, lid = threadIdx.x & 31;
    if (lid == 0) { rs[wid] = s; rss[wid] = ss; }
    __syncthreads();
    if (threadIdx.x == 0) {
        float ts = 0.f, tss = 0.f;
        #pragma unroll
        for (int w = 0; w < 8; w++) { ts += rs[w]; tss += rss[w]; }
        part[blockIdx.x * 2 + 0] = ts;
        part[blockIdx.x * 2 + 1] = tss;
    }
}

// ---------------- GroupNorm: normalize + affine (float4) ---------------------
// grid: 1024 blocks, 256 threads, each thread one float4 (block = 1024 elems,
// always within one channel since N=4096)
__global__ void gn_norm_kernel(const float* __restrict__ x,
                               const float* __restrict__ gamma,
                               const float* __restrict__ beta,
                               const float* __restrict__ part,
                               float* __restrict__ hout) {
    int b = blockIdx.x;
    int c = b >> 2;             // b*1024 / 4096
    int g = c >> 5;             // c / 32
    __shared__ float sm_scale, sm_shift;
    if (threadIdx.x == 0) {
        float s = 0.f, ss = 0.f;
        #pragma unroll
        for (int t = 0; t < 8; t++) {
            s  += part[(g * 8 + t) * 2 + 0];
            ss += part[(g * 8 + t) * 2 + 1];
        }
        float mean = s * (1.0f / GSIZE);
        float var  = ss * (1.0f / GSIZE) - mean * mean;
        float inv  = rsqrtf(var + EPSV);
        float ga   = gamma[c] * inv;
        sm_scale = ga;
        sm_shift = beta[c] - mean * ga;
    }
    __syncthreads();
    float sc = sm_scale, sh = sm_shift;
    int idx4 = b * 256 + threadIdx.x;
    float4 v = ((const float4*)x)[idx4];
    float4 o;
    o.x = v.x * sc + sh; o.y = v.y * sc + sh;
    o.z = v.z * sc + sh; o.w = v.w * sc + sh;
    ((float4*)hout)[idx4] = o;
}

// ---------------- Tiled fp32 GEMM: Y[M][N] = W[M][K] @ H[K][N] + b (+res) ----
#define BM 64
#define BN 64
#define BK 16
__global__ void gemm_kernel(const float* __restrict__ W, const float* __restrict__ Hm,
                            const float* __restrict__ bias, const float* __restrict__ res,
                            float* __restrict__ Y, int M, int Nn, int K) {
    __shared__ float As[BK][BM + 1];
    __shared__ float Bs[BK][BN + 1];
    int tid = threadIdx.x;              // 256
    int m0 = blockIdx.y * BM, n0 = blockIdx.x * BN;
    int ty = tid >> 4, tx = tid & 15;
    float acc[4][4] = {};

    for (int k0 = 0; k0 < K; k0 += BK) {
        #pragma unroll
        for (int i = 0; i < 4; i++) {
            int idx = tid + i * 256;
            int m = idx >> 4, k = idx & 15;
            As[k][m] = W[(m0 + m) * K + k0 + k];
        }
        #pragma unroll
        for (int i = 0; i < 4; i++) {
            int idx = tid + i * 256;
            int k = idx >> 6, n = idx & 63;
            Bs[k][n] = Hm[(k0 + k) * Nn + n0 + n];
        }
        __syncthreads();
        #pragma unroll
        for (int k = 0; k < BK; k++) {
            float a[4], bvec[4];
            #pragma unroll
            for (int i = 0; i < 4; i++) a[i] = As[k][ty * 4 + i];
            #pragma unroll
            for (int j = 0; j < 4; j++) bvec[j] = Bs[k][tx * 4 + j];
            #pragma unroll
            for (int i = 0; i < 4; i++)
                #pragma unroll
                for (int j = 0; j < 4; j++)
                    acc[i][j] += a[i] * bvec[j];
        }
        __syncthreads();
    }
    #pragma unroll
    for (int i = 0; i < 4; i++) {
        int m = m0 + ty * 4 + i;
        float bv = bias[m];
        #pragma unroll
        for (int j = 0; j < 4; j++) {
            int n = n0 + tx * 4 + j;
            float v = acc[i][j] + bv;
            if (res) v += res[m * Nn + n];
            Y[m * Nn + n] = v;
        }
    }
}

// ---------------- Flash attention: 1 thread = 1 query ------------------------
#define QT 128
#define KT 64
#define KPAD 36   // 36*4=144 bytes, 16B aligned rows; 4-way write conflicts only
__global__ void attn_kernel(const float* __restrict__ qkv, float* __restrict__ outp) {
    __shared__ float Ks[KT][KPAD];
    __shared__ float Vs[KT][KPAD];
    const int head = blockIdx.y;
    const int qi = blockIdx.x * QT + threadIdx.x;
    const float* Qp = qkv + (head * HDIM) * N_TOK;
    const float* Kp = qkv + (C_DIM + head * HDIM) * N_TOK;
    const float* Vp = qkv + (2 * C_DIM + head * HDIM) * N_TOK;
    const float scale = 0.17677669529663687f;  // 1/sqrt(32)

    float q[HDIM];
    #pragma unroll
    for (int d = 0; d < HDIM; d++) q[d] = Qp[d * N_TOK + qi] * scale;
    float o[HDIM];
    #pragma unroll
    for (int d = 0; d < HDIM; d++) o[d] = 0.f;
    float m = -1e30f, l = 0.f;

    for (int k0 = 0; k0 < N_TOK; k0 += KT) {
        // cooperative tile load: coalesced global reads, transposed smem write
        for (int idx = threadIdx.x; idx < KT * HDIM; idx += QT) {
            int d = idx / KT, j = idx % KT;
            Ks[j][d] = Kp[d * N_TOK + k0 + j];
            Vs[j][d] = Vp[d * N_TOK + k0 + j];
        }
        __syncthreads();

        for (int j = 0; j < KT; j++) {
            const float4* kr = (const float4*)&Ks[j][0];
            float s0 = 0.f, s1 = 0.f, s2 = 0.f, s3 = 0.f;
            #pragma unroll
            for (int t = 0; t < 8; t++) {
                float4 kv = kr[t];
                s0 += q[4 * t + 0] * kv.x;
                s1 += q[4 * t + 1] * kv.y;
                s2 += q[4 * t + 2] * kv.z;
                s3 += q[4 * t + 3] * kv.w;
            }
            float s = (s0 + s1) + (s2 + s3);

            if (s > m) {                     // rescale only when max moves
                float corr = __expf(m - s);
                m = s;
                l *= corr;
                #pragma unroll
                for (int d = 0; d < HDIM; d++) o[d] *= corr;
            }
            float p = __expf(s - m);
            l += p;
            const float4* vr = (const float4*)&Vs[j][0];
            #pragma unroll
            for (int t = 0; t < 8; t++) {
                float4 vv = vr[t];
                o[4 * t + 0] += p * vv.x;
                o[4 * t + 1] += p * vv.y;
                o[4 * t + 2] += p * vv.z;
                o[4 * t + 3] += p * vv.w;
            }
        }
        __syncthreads();
    }
    float inv = 1.f / l;
    #pragma unroll
    for (int d = 0; d < HDIM; d++)
        outp[(head * HDIM + d) * N_TOK + qi] = o[d] * inv;
}

// ---------------- launcher ---------------------------------------------------
extern "C" void kernel_launch(void* const* d_in, const int* in_sizes, int n_in,
                              void* d_out, int out_size) {
    const float* x      = (const float*)d_in[0];
    const float* gamma  = (const float*)d_in[1];
    const float* beta   = (const float*)d_in[2];
    const float* qkv_w  = (const float*)d_in[3];
    const float* qkv_b  = (const float*)d_in[4];
    const float* proj_w = (const float*)d_in[5];
    const float* proj_b = (const float*)d_in[6];
    float* out = (float*)d_out;

    float *p_part, *p_h, *p_qkv, *p_attn;
    cudaGetSymbolAddress((void**)&p_part, g_part);
    cudaGetSymbolAddress((void**)&p_h,    g_h);
    cudaGetSymbolAddress((void**)&p_qkv,  g_qkv);
    cudaGetSymbolAddress((void**)&p_attn, g_attn);

    // 1. GroupNorm
    gn_stats_kernel<<<64, 256>>>(x, p_part);
    gn_norm_kernel<<<1024, 256>>>(x, gamma, beta, p_part, p_h);

    // 2. QKV GEMM: [768,256] @ [256,4096]
    gemm_kernel<<<dim3(N_TOK / BN, (3 * C_DIM) / BM), 256>>>(
        qkv_w, p_h, qkv_b, nullptr, p_qkv, 3 * C_DIM, N_TOK, C_DIM);

    // 3. Attention
    attn_kernel<<<dim3(N_TOK / QT, HEADS), QT>>>(p_qkv, p_attn);

    // 4. Proj GEMM + bias + residual -> d_out
    gemm_kernel<<<dim3(N_TOK / BN, C_DIM / BM), 256>>>(
        proj_w, p_attn, proj_b, x, out, C_DIM, N_TOK, C_DIM);
}

// round 2
// speedup vs baseline: 1.3877x; 1.3877x over previous
#include <cuda_runtime.h>
#include <math.h>

// Problem constants
#define C_DIM   256
#define N_TOK   4096
#define GROUPS  8
#define CPG     (C_DIM / GROUPS)        // 32
#define HEADS   8
#define HDIM    32
#define EPSV    1e-5f
#define GSIZE   (CPG * N_TOK)           // 131072 elems per group
#define SPLIT   4
#define KEYS_PER_SPLIT (N_TOK / SPLIT)  // 1024

typedef unsigned long long ull;

// ---------------- scratch (static device globals; no allocation) -------------
__device__ float g_part[64][2];                    // groupnorm partial (sum, sumsq)
__device__ float g_h[C_DIM * N_TOK];               // groupnorm output  [C][N]
__device__ float g_qkv[3 * C_DIM * N_TOK];         // qkv               [3C][N]
__device__ float g_attn[C_DIM * N_TOK];            // attention output  [C][N]
__device__ float g_po[SPLIT * HEADS * HDIM * N_TOK]; // partial o (unnormalized)
__device__ float g_pm[SPLIT * HEADS * N_TOK];        // partial max
__device__ float g_pl[SPLIT * HEADS * N_TOK];        // partial denom

// ---------------- packed f32x2 helpers ---------------------------------------
__device__ __forceinline__ ull pk2(float lo, float hi) {
    ull r;
    asm("mov.b64 %0, {%1,%2};" : "=l"(r) : "f"(lo), "f"(hi));
    return r;
}
__device__ __forceinline__ float2 upk2(ull v) {
    float2 r;
    asm("mov.b64 {%0,%1}, %2;" : "=f"(r.x), "=f"(r.y) : "l"(v));
    return r;
}
__device__ __forceinline__ void fma2(ull &d, ull a, ull b) {
    asm("fma.rn.f32x2 %0, %1, %2, %0;" : "+l"(d) : "l"(a), "l"(b));
}
__device__ __forceinline__ void mul2(ull &d, ull a) {
    asm("mul.rn.f32x2 %0, %0, %1;" : "+l"(d) : "l"(a));
}
__device__ __forceinline__ void add2(ull &d, ull a) {
    asm("add.rn.f32x2 %0, %0, %1;" : "+l"(d) : "l"(a));
}

// ---------------- GroupNorm: partial stats ------------------------------------
__global__ void gn_stats_kernel(const float* __restrict__ x, float* __restrict__ part) {
    int g  = blockIdx.x >> 3;
    int sl = blockIdx.x & 7;
    const float* xg = x + g * GSIZE + sl * (GSIZE / 8);
    float s = 0.f, ss = 0.f;
    for (int i = threadIdx.x; i < GSIZE / 8; i += 256) {
        float v = xg[i];
        s += v; ss += v * v;
    }
    for (int o = 16; o > 0; o >>= 1) {
        s  += __shfl_down_sync(0xffffffff, s,  o);
        ss += __shfl_down_sync(0xffffffff, ss, o);
    }
    __shared__ float rs[8], rss[8];
    int wid = threadIdx.x >> 5, lid = threadIdx.x & 31;
    if (lid == 0) { rs[wid] = s; rss[wid] = ss; }
    __syncthreads();
    if (threadIdx.x == 0) {
        float ts = 0.f, tss = 0.f;
        #pragma unroll
        for (int w = 0; w < 8; w++) { ts += rs[w]; tss += rss[w]; }
        part[blockIdx.x * 2 + 0] = ts;
        part[blockIdx.x * 2 + 1] = tss;
    }
}

// ---------------- GroupNorm: normalize + affine -------------------------------
__global__ void gn_norm_kernel(const float* __restrict__ x,
                               const float* __restrict__ gamma,
                               const float* __restrict__ beta,
                               const float* __restrict__ part,
                               float* __restrict__ hout) {
    int b = blockIdx.x;
    int c = b >> 2;
    int g = c >> 5;
    __shared__ float sm_scale, sm_shift;
    if (threadIdx.x == 0) {
        float s = 0.f, ss = 0.f;
        #pragma unroll
        for (int t = 0; t < 8; t++) {
            s  += part[(g * 8 + t) * 2 + 0];
            ss += part[(g * 8 + t) * 2 + 1];
        }
        float mean = s * (1.0f / GSIZE);
        float var  = ss * (1.0f / GSIZE) - mean * mean;
        float inv  = rsqrtf(var + EPSV);
        float ga   = gamma[c] * inv;
        sm_scale = ga;
        sm_shift = beta[c] - mean * ga;
    }
    __syncthreads();
    float sc = sm_scale, sh = sm_shift;
    int idx4 = b * 256 + threadIdx.x;
    float4 v = ((const float4*)x)[idx4];
    float4 o;
    o.x = v.x * sc + sh; o.y = v.y * sc + sh;
    o.z = v.z * sc + sh; o.w = v.w * sc + sh;
    ((float4*)hout)[idx4] = o;
}

// ---------------- Tiled fp32 GEMM ---------------------------------------------
#define BM 64
#define BN 64
#define BK 16
__global__ void gemm_kernel(const float* __restrict__ W, const float* __restrict__ Hm,
                            const float* __restrict__ bias, const float* __restrict__ res,
                            float* __restrict__ Y, int M, int Nn, int K) {
    __shared__ float As[BK][BM + 1];
    __shared__ float Bs[BK][BN + 1];
    int tid = threadIdx.x;
    int m0 = blockIdx.y * BM, n0 = blockIdx.x * BN;
    int ty = tid >> 4, tx = tid & 15;
    float acc[4][4] = {};

    for (int k0 = 0; k0 < K; k0 += BK) {
        #pragma unroll
        for (int i = 0; i < 4; i++) {
            int idx = tid + i * 256;
            int m = idx >> 4, k = idx & 15;
            As[k][m] = W[(m0 + m) * K + k0 + k];
        }
        #pragma unroll
        for (int i = 0; i < 4; i++) {
            int idx = tid + i * 256;
            int k = idx >> 6, n = idx & 63;
            Bs[k][n] = Hm[(k0 + k) * Nn + n0 + n];
        }
        __syncthreads();
        #pragma unroll
        for (int k = 0; k < BK; k++) {
            float a[4], bvec[4];
            #pragma unroll
            for (int i = 0; i < 4; i++) a[i] = As[k][ty * 4 + i];
            #pragma unroll
            for (int j = 0; j < 4; j++) bvec[j] = Bs[k][tx * 4 + j];
            #pragma unroll
            for (int i = 0; i < 4; i++)
                #pragma unroll
                for (int j = 0; j < 4; j++)
                    acc[i][j] += a[i] * bvec[j];
        }
        __syncthreads();
    }
    #pragma unroll
    for (int i = 0; i < 4; i++) {
        int m = m0 + ty * 4 + i;
        float bv = bias[m];
        #pragma unroll
        for (int j = 0; j < 4; j++) {
            int n = n0 + tx * 4 + j;
            float v = acc[i][j] + bv;
            if (res) v += res[m * Nn + n];
            Y[m * Nn + n] = v;
        }
    }
}

// ---------------- Flash attention (split-KV, packed f32x2) --------------------
#define QT 128
#define KT 64
#define KPAD 36   // 36 floats = 144B row stride, 16B aligned
__global__ __launch_bounds__(QT) void attn_kernel(const float* __restrict__ qkv,
                                                  float* __restrict__ po,
                                                  float* __restrict__ pm,
                                                  float* __restrict__ pl) {
    __shared__ __align__(16) float Ks[KT][KPAD];
    __shared__ __align__(16) float Vs[KT][KPAD];
    const int head  = blockIdx.y;
    const int split = blockIdx.z;
    const int qi = blockIdx.x * QT + threadIdx.x;
    const float* Qp = qkv + (head * HDIM) * N_TOK;
    const float* Kp = qkv + (C_DIM + head * HDIM) * N_TOK;
    const float* Vp = qkv + (2 * C_DIM + head * HDIM) * N_TOK;
    const float scale = 0.17677669529663687f;  // 1/sqrt(32)

    ull q2[16];
    #pragma unroll
    for (int t = 0; t < 16; t++)
        q2[t] = pk2(Qp[(2 * t) * N_TOK + qi] * scale,
                    Qp[(2 * t + 1) * N_TOK + qi] * scale);
    ull o2[16];
    #pragma unroll
    for (int t = 0; t < 16; t++) o2[t] = 0ull;   // two packed +0.0f
    float m = -1e30f, l = 0.f;

    const int kbase = split * KEYS_PER_SPLIT;
    for (int k0 = kbase; k0 < kbase + KEYS_PER_SPLIT; k0 += KT) {
        for (int idx = threadIdx.x; idx < KT * HDIM; idx += QT) {
            int d = idx / KT, j = idx % KT;
            Ks[j][d] = Kp[d * N_TOK + k0 + j];
            Vs[j][d] = Vp[d * N_TOK + k0 + j];
        }
        __syncthreads();

        for (int j = 0; j < KT; j++) {
            const ulonglong2* kr = (const ulonglong2*)&Ks[j][0];
            ull a0 = 0ull, a1 = 0ull, a2 = 0ull, a3 = 0ull;
            #pragma unroll
            for (int t = 0; t < 8; t += 2) {
                ulonglong2 kva = kr[t];
                ulonglong2 kvb = kr[t + 1];
                fma2(a0, q2[2 * t + 0], kva.x);
                fma2(a1, q2[2 * t + 1], kva.y);
                fma2(a2, q2[2 * t + 2], kvb.x);
                fma2(a3, q2[2 * t + 3], kvb.y);
            }
            add2(a0, a1); add2(a2, a3); add2(a0, a2);
            float2 sf = upk2(a0);
            float s = sf.x + sf.y;

            if (s > m) {                    // rescale only when max moves
                float corr = __expf(m - s);
                m = s;
                l *= corr;
                ull c2 = pk2(corr, corr);
                #pragma unroll
                for (int t = 0; t < 16; t++) mul2(o2[t], c2);
            }
            float p = __expf(s - m);
            l += p;
            ull p2 = pk2(p, p);
            const ulonglong2* vr = (const ulonglong2*)&Vs[j][0];
            #pragma unroll
            for (int t = 0; t < 8; t++) {
                ulonglong2 vv = vr[t];
                fma2(o2[2 * t + 0], p2, vv.x);
                fma2(o2[2 * t + 1], p2, vv.y);
            }
        }
        __syncthreads();
    }

    const int sidx = split * HEADS + head;
    pm[sidx * N_TOK + qi] = m;
    pl[sidx * N_TOK + qi] = l;
    float* pob = po + (sidx * HDIM) * N_TOK + qi;
    #pragma unroll
    for (int t = 0; t < 16; t++) {
        float2 v = upk2(o2[t]);
        pob[(2 * t) * N_TOK]     = v.x;
        pob[(2 * t + 1) * N_TOK] = v.y;
    }
}

// ---------------- combine split-KV partials -----------------------------------
__global__ void attn_combine_kernel(const float* __restrict__ po,
                                    const float* __restrict__ pm,
                                    const float* __restrict__ pl,
                                    float* __restrict__ outp) {
    int gid  = blockIdx.x * 256 + threadIdx.x;   // 0..32767
    int head = gid >> 12;
    int qi   = gid & (N_TOK - 1);

    float mi[SPLIT], w[SPLIT];
    float M = -1e30f;
    #pragma unroll
    for (int i = 0; i < SPLIT; i++) {
        mi[i] = pm[(i * HEADS + head) * N_TOK + qi];
        M = fmaxf(M, mi[i]);
    }
    float L = 0.f;
    #pragma unroll
    for (int i = 0; i < SPLIT; i++) {
        w[i] = __expf(mi[i] - M);
        L += pl[(i * HEADS + head) * N_TOK + qi] * w[i];
    }
    float inv = 1.f / L;
    #pragma unroll
    for (int i = 0; i < SPLIT; i++) w[i] *= inv;

    #pragma unroll
    for (int d = 0; d < HDIM; d++) {
        float s = 0.f;
        #pragma unroll
        for (int i = 0; i < SPLIT; i++)
            s += po[((i * HEADS + head) * HDIM + d) * N_TOK + qi] * w[i];
        outp[(head * HDIM + d) * N_TOK + qi] = s;
    }
}

// ---------------- launcher ----------------------------------------------------
extern "C" void kernel_launch(void* const* d_in, const int* in_sizes, int n_in,
                              void* d_out, int out_size) {
    const float* x      = (const float*)d_in[0];
    const float* gamma  = (const float*)d_in[1];
    const float* beta   = (const float*)d_in[2];
    const float* qkv_w  = (const float*)d_in[3];
    const float* qkv_b  = (const float*)d_in[4];
    const float* proj_w = (const float*)d_in[5];
    const float* proj_b = (const float*)d_in[6];
    float* out = (float*)d_out;

    float *p_part, *p_h, *p_qkv, *p_attn, *p_po, *p_pm, *p_pl;
    cudaGetSymbolAddress((void**)&p_part, g_part);
    cudaGetSymbolAddress((void**)&p_h,    g_h);
    cudaGetSymbolAddress((void**)&p_qkv,  g_qkv);
    cudaGetSymbolAddress((void**)&p_attn, g_attn);
    cudaGetSymbolAddress((void**)&p_po,   g_po);
    cudaGetSymbolAddress((void**)&p_pm,   g_pm);
    cudaGetSymbolAddress((void**)&p_pl,   g_pl);

    // 1. GroupNorm
    gn_stats_kernel<<<64, 256>>>(x, p_part);
    gn_norm_kernel<<<1024, 256>>>(x, gamma, beta, p_part, p_h);

    // 2. QKV GEMM: [768,256] @ [256,4096]
    gemm_kernel<<<dim3(N_TOK / BN, (3 * C_DIM) / BM), 256>>>(
        qkv_w, p_h, qkv_b, nullptr, p_qkv, 3 * C_DIM, N_TOK, C_DIM);

    // 3. Attention (split-KV x4) + combine
    attn_kernel<<<dim3(N_TOK / QT, HEADS, SPLIT), QT>>>(p_qkv, p_po, p_pm, p_pl);
    attn_combine_kernel<<<(N_TOK * HEADS) / 256, 256>>>(p_po, p_pm, p_pl, p_attn);

    // 4. Proj GEMM + bias + residual -> d_out
    gemm_kernel<<<dim3(N_TOK / BN, C_DIM / BM), 256>>>(
        proj_w, p_attn, proj_b, x, out, C_DIM, N_TOK, C_DIM);
}